// round 13
// baseline (speedup 1.0000x reference)
#include <cuda_runtime.h>
#include <cstdint>

#define B_   256
#define L_   512
#define LA_  8
#define LLF_ 64
#define V_   100000
#define D_   300
#define P_   3
#define D4_  75

// ---------------- device scratch ----------------
__device__ __align__(16) float g_asp_e[B_ * D_];
__device__ __align__(16) float g_sumvec[B_ * D_];
__device__ __align__(16) float g_matt[B_ * D_];
__device__ int   g_len[B_ * 3];
__device__ __align__(16) float g_u[D_];
__device__ __align__(16) float g_v[D_];
__device__ __align__(16) float g_t1[D_];
__device__ __align__(16) float g_t2[D_];
__device__ __align__(16) float g_wv[D_];
__device__ float g_sc[2];

// ---------------- combo: blocks 0..30 vec-part, blocks 31..286 prep-part --------
__global__ void combo_kernel(const int* __restrict__ text,
                             const int* __restrict__ aspect,
                             const int* __restrict__ left,
                             const float* __restrict__ embed,
                             const float* __restrict__ Wk,
                             const float* __restrict__ bk,
                             const float* __restrict__ Wq,
                             const float* __restrict__ bq,
                             const float* __restrict__ w_mlp) {
    int tid = threadIdx.x;
    if (blockIdx.x < 31) {
        int warp = tid >> 5, lane = tid & 31;
        int gw = blockIdx.x * 10 + warp;
        if (gw < D_) {
            float u = 0.f, q = 0.f;
            int base = gw * D_;
#pragma unroll
            for (int k = 0; k < 9; k++) {
                int j = lane + 32 * k;
                u = fmaf(Wk[base + j], w_mlp[j], u);
                q = fmaf(Wq[base + j], w_mlp[D_ + j], q);
            }
            if (lane < 12) {
                int j = 288 + lane;
                u = fmaf(Wk[base + j], w_mlp[j], u);
                q = fmaf(Wq[base + j], w_mlp[D_ + j], q);
            }
#pragma unroll
            for (int off = 16; off; off >>= 1) {
                u += __shfl_xor_sync(0xffffffffu, u, off);
                q += __shfl_xor_sync(0xffffffffu, q, off);
            }
            if (lane == 0) { g_u[gw] = u; g_v[gw] = q; }
        } else if (gw == D_ || gw == D_ + 1) {
            const float* v1 = (gw == D_) ? bk : bq;
            const float* v2 = (gw == D_) ? w_mlp : (w_mlp + D_);
            float s = 0.f;
            for (int j = lane; j < D_; j += 32) s = fmaf(v1[j], v2[j], s);
#pragma unroll
            for (int off = 16; off; off >>= 1) s += __shfl_xor_sync(0xffffffffu, s, off);
            if (lane == 0) g_sc[gw - D_] = s;
        }
    } else {
        int b = blockIdx.x - 31;
        __shared__ int cnt[3];
        if (tid < 3) cnt[tid] = 0;
        __syncthreads();
        int c0 = 0;
        for (int l = tid; l < L_; l += 320) c0 += (text[b * L_ + l] != 0);
        int c1 = (tid < LA_) ? (aspect[b * LA_ + tid] != 0) : 0;
        int c2 = 0;
        for (int l = tid; l < LLF_; l += 320) c2 += (left[b * LLF_ + l] != 0);
        if (c0) atomicAdd(&cnt[0], c0);
        if (c1) atomicAdd(&cnt[1], c1);
        if (c2) atomicAdd(&cnt[2], c2);
        __syncthreads();
        if (tid < 3) g_len[b * 3 + tid] = cnt[tid];
        if (tid < D_) {
            float s = 0.f;
#pragma unroll
            for (int j = 0; j < LA_; j++) {
                int tok = aspect[b * LA_ + j];
                s += embed[(long)tok * D_ + tid];
            }
            g_asp_e[b * D_ + tid] = s / (float)cnt[1];
        }
    }
}

// ---------------- mv: out = Wx @ in (warp per row, wide grid) ----------------
__global__ void mv_kernel(const float* __restrict__ Wx, int step) {
    const float* in  = (step == 0) ? g_v : ((step == 1) ? g_t1 : g_t2);
    float*       out = (step == 0) ? g_t1 : ((step == 1) ? g_t2 : g_wv);
    int warp = threadIdx.x >> 5, lane = threadIdx.x & 31;
    int row = blockIdx.x * 10 + warp;
    if (row >= D_) return;
    int base = row * D_;
    float s = 0.f;
#pragma unroll
    for (int k = 0; k < 9; k++) {
        int j = lane + 32 * k;
        s = fmaf(Wx[base + j], in[j], s);
    }
    if (lane < 12) s = fmaf(Wx[base + 288 + lane], in[288 + lane], s);
#pragma unroll
    for (int off = 16; off; off >>= 1) s += __shfl_xor_sync(0xffffffffu, s, off);
    if (lane == 0) out[row] = s;
}

// ---------------- fused: qs-dot + dots + raw sum + softmax + weighted gather ----
// (round-8/11 proven version: inline shfl dot reduction)
__global__ void __launch_bounds__(512, 2)
fused_kernel(const int* __restrict__ text, const float4* __restrict__ embed4) {
    __shared__ float4 su[D4_ + 1];
    __shared__ float red[D_];
    __shared__ float sc[L_];
    __shared__ int   tok_s[L_];
    __shared__ float rbuf[20];
    int tid = threadIdx.x, b = blockIdx.x;
    int warp = tid >> 5, lane = tid & 31;

    if (tid < D4_) su[tid] = reinterpret_cast<const float4*>(g_u)[tid];
    if (tid == D4_) su[D4_] = make_float4(0.f, 0.f, 0.f, 0.f);
    if (tid < D_) red[tid] = 0.f;
    tok_s[tid] = text[b * L_ + tid];
    // warp 0: qs = asp_e[b] · g_wv
    if (warp == 0) {
        float s = 0.f;
        int base = b * D_;
#pragma unroll
        for (int k = 0; k < 9; k++) {
            int j = lane + 32 * k;
            s = fmaf(g_asp_e[base + j], g_wv[j], s);
        }
        if (lane < 12) s = fmaf(g_asp_e[base + 288 + lane], g_wv[288 + lane], s);
#pragma unroll
        for (int off = 16; off; off >>= 1) s += __shfl_xor_sync(0xffffffffu, s, off);
        if (lane == 0) rbuf[18] = s;
    }
    __syncthreads();

    float memf  = (float)g_len[b * 3 + 0];
    float start = (float)(g_len[b * 3 + 2] - g_len[b * 3 + 1]);
    float endf  = (float)g_len[b * 3 + 2];
    float qs = rbuf[18] + g_sc[1];
    float cc = g_sc[0];
    float inv_memf = 1.f / memf;

    int half = lane >> 4, sub = lane & 15;
    int l0 = warp * 32;
    int last = (sub < 11) ? (sub + 64) : (D4_ - 1);

    float4 u0 = su[sub], u1 = su[sub + 16], u2 = su[sub + 32], u3 = su[sub + 48];
    float4 u4 = (sub < 11) ? su[sub + 64] : make_float4(0.f, 0.f, 0.f, 0.f);

    float4 a0 = make_float4(0.f,0.f,0.f,0.f), a1 = a0, a2 = a0, a3 = a0, a4 = a0;

    // ---- phase 1: dots (inline reduce) + raw sum ----
#pragma unroll 4
    for (int it = 0; it < 16; it++) {
        int l = l0 + 2 * it + half;
        int tok = tok_s[l];
        const float4* row = embed4 + (long)tok * D4_;
        float4 v0 = row[sub];
        float4 v1 = row[sub + 16];
        float4 v2 = row[sub + 32];
        float4 v3 = row[sub + 48];
        float4 v4 = row[last];
        if (sub >= 11) v4 = make_float4(0.f, 0.f, 0.f, 0.f);

        float d = v0.x*u0.x + v0.y*u0.y + v0.z*u0.z + v0.w*u0.w
                + v1.x*u1.x + v1.y*u1.y + v1.z*u1.z + v1.w*u1.w
                + v2.x*u2.x + v2.y*u2.y + v2.z*u2.z + v2.w*u2.w
                + v3.x*u3.x + v3.y*u3.y + v3.z*u3.z + v3.w*u3.w
                + v4.x*u4.x + v4.y*u4.y + v4.z*u4.z + v4.w*u4.w;

        a0.x += v0.x; a0.y += v0.y; a0.z += v0.z; a0.w += v0.w;
        a1.x += v1.x; a1.y += v1.y; a1.z += v1.z; a1.w += v1.w;
        a2.x += v2.x; a2.y += v2.y; a2.z += v2.z; a2.w += v2.w;
        a3.x += v3.x; a3.y += v3.y; a3.z += v3.z; a3.w += v3.w;
        a4.x += v4.x; a4.y += v4.y; a4.z += v4.z; a4.w += v4.w;

#pragma unroll
        for (int off = 8; off; off >>= 1) d += __shfl_xor_sync(0xffffffffu, d, off);
        if (sub == 0) sc[l] = d;
    }
    a0.x += __shfl_xor_sync(0xffffffffu, a0.x, 16); a0.y += __shfl_xor_sync(0xffffffffu, a0.y, 16);
    a0.z += __shfl_xor_sync(0xffffffffu, a0.z, 16); a0.w += __shfl_xor_sync(0xffffffffu, a0.w, 16);
    a1.x += __shfl_xor_sync(0xffffffffu, a1.x, 16); a1.y += __shfl_xor_sync(0xffffffffu, a1.y, 16);
    a1.z += __shfl_xor_sync(0xffffffffu, a1.z, 16); a1.w += __shfl_xor_sync(0xffffffffu, a1.w, 16);
    a2.x += __shfl_xor_sync(0xffffffffu, a2.x, 16); a2.y += __shfl_xor_sync(0xffffffffu, a2.y, 16);
    a2.z += __shfl_xor_sync(0xffffffffu, a2.z, 16); a2.w += __shfl_xor_sync(0xffffffffu, a2.w, 16);
    a3.x += __shfl_xor_sync(0xffffffffu, a3.x, 16); a3.y += __shfl_xor_sync(0xffffffffu, a3.y, 16);
    a3.z += __shfl_xor_sync(0xffffffffu, a3.z, 16); a3.w += __shfl_xor_sync(0xffffffffu, a3.w, 16);
    a4.x += __shfl_xor_sync(0xffffffffu, a4.x, 16); a4.y += __shfl_xor_sync(0xffffffffu, a4.y, 16);
    a4.z += __shfl_xor_sync(0xffffffffu, a4.z, 16); a4.w += __shfl_xor_sync(0xffffffffu, a4.w, 16);
    if (half == 0) {
        int p0 = 4 * sub;
        atomicAdd(&red[p0 + 0], a0.x); atomicAdd(&red[p0 + 1], a0.y);
        atomicAdd(&red[p0 + 2], a0.z); atomicAdd(&red[p0 + 3], a0.w);
        int p1 = 4 * (sub + 16);
        atomicAdd(&red[p1 + 0], a1.x); atomicAdd(&red[p1 + 1], a1.y);
        atomicAdd(&red[p1 + 2], a1.z); atomicAdd(&red[p1 + 3], a1.w);
        int p2 = 4 * (sub + 32);
        atomicAdd(&red[p2 + 0], a2.x); atomicAdd(&red[p2 + 1], a2.y);
        atomicAdd(&red[p2 + 2], a2.z); atomicAdd(&red[p2 + 3], a2.w);
        int p3 = 4 * (sub + 48);
        atomicAdd(&red[p3 + 0], a3.x); atomicAdd(&red[p3 + 1], a3.y);
        atomicAdd(&red[p3 + 2], a3.z); atomicAdd(&red[p3 + 3], a3.w);
        if (sub < 11) {
            int p4 = 4 * (sub + 64);
            atomicAdd(&red[p4 + 0], a4.x); atomicAdd(&red[p4 + 1], a4.y);
            atomicAdd(&red[p4 + 2], a4.z); atomicAdd(&red[p4 + 3], a4.w);
        }
    }
    __syncthreads();
    if (tid < D_) { g_sumvec[b * D_ + tid] = red[tid]; red[tid] = 0.f; }

    // ---- softmax over L in-block ----
    float idx = (float)tid;
    float lv = idx < start ? (start - idx) : (idx <= endf ? 0.f : idx - endf);
    float wv = 1.f - lv * inv_memf;
    if (!(idx < memf)) wv = 0.f;
    float logit = tanhf(sc[tid] * wv + cc + qs);

    float m = logit;
#pragma unroll
    for (int off = 16; off; off >>= 1) m = fmaxf(m, __shfl_xor_sync(0xffffffffu, m, off));
    if (lane == 0) rbuf[warp] = m;
    __syncthreads();
    if (warp == 0) {
        float mm = (lane < 16) ? rbuf[lane] : -1e30f;
#pragma unroll
        for (int off = 16; off; off >>= 1) mm = fmaxf(mm, __shfl_xor_sync(0xffffffffu, mm, off));
        if (lane == 0) rbuf[16] = mm;
    }
    __syncthreads();
    m = rbuf[16];
    float e = expf(logit - m);
    float s = e;
#pragma unroll
    for (int off = 16; off; off >>= 1) s += __shfl_xor_sync(0xffffffffu, s, off);
    if (lane == 0) rbuf[warp] = s;
    __syncthreads();
    if (warp == 0) {
        float ss = (lane < 16) ? rbuf[lane] : 0.f;
#pragma unroll
        for (int off = 16; off; off >>= 1) ss += __shfl_xor_sync(0xffffffffu, ss, off);
        if (lane == 0) rbuf[17] = ss;
    }
    __syncthreads();
    float inv = 1.f / rbuf[17];
    sc[tid] = e * inv * wv;
    __syncthreads();

    // ---- phase 2: weighted gather (rows hot in L1/L2) ----
    a0 = make_float4(0.f,0.f,0.f,0.f); a1 = a0; a2 = a0; a3 = a0; a4 = a0;
#pragma unroll 4
    for (int it = 0; it < 16; it++) {
        int l = l0 + 2 * it + half;
        float swv = sc[l];
        if (swv != 0.f) {
            int tok = tok_s[l];
            const float4* row = embed4 + (long)tok * D4_;
            float4 v0 = row[sub];
            float4 v1 = row[sub + 16];
            float4 v2 = row[sub + 32];
            float4 v3 = row[sub + 48];
            float4 v4 = row[last];
            a0.x = fmaf(swv, v0.x, a0.x); a0.y = fmaf(swv, v0.y, a0.y);
            a0.z = fmaf(swv, v0.z, a0.z); a0.w = fmaf(swv, v0.w, a0.w);
            a1.x = fmaf(swv, v1.x, a1.x); a1.y = fmaf(swv, v1.y, a1.y);
            a1.z = fmaf(swv, v1.z, a1.z); a1.w = fmaf(swv, v1.w, a1.w);
            a2.x = fmaf(swv, v2.x, a2.x); a2.y = fmaf(swv, v2.y, a2.y);
            a2.z = fmaf(swv, v2.z, a2.z); a2.w = fmaf(swv, v2.w, a2.w);
            a3.x = fmaf(swv, v3.x, a3.x); a3.y = fmaf(swv, v3.y, a3.y);
            a3.z = fmaf(swv, v3.z, a3.z); a3.w = fmaf(swv, v3.w, a3.w);
            if (sub < 11) {
                a4.x = fmaf(swv, v4.x, a4.x); a4.y = fmaf(swv, v4.y, a4.y);
                a4.z = fmaf(swv, v4.z, a4.z); a4.w = fmaf(swv, v4.w, a4.w);
            }
        }
    }
    a0.x += __shfl_xor_sync(0xffffffffu, a0.x, 16); a0.y += __shfl_xor_sync(0xffffffffu, a0.y, 16);
    a0.z += __shfl_xor_sync(0xffffffffu, a0.z, 16); a0.w += __shfl_xor_sync(0xffffffffu, a0.w, 16);
    a1.x += __shfl_xor_sync(0xffffffffu, a1.x, 16); a1.y += __shfl_xor_sync(0xffffffffu, a1.y, 16);
    a1.z += __shfl_xor_sync(0xffffffffu, a1.z, 16); a1.w += __shfl_xor_sync(0xffffffffu, a1.w, 16);
    a2.x += __shfl_xor_sync(0xffffffffu, a2.x, 16); a2.y += __shfl_xor_sync(0xffffffffu, a2.y, 16);
    a2.z += __shfl_xor_sync(0xffffffffu, a2.z, 16); a2.w += __shfl_xor_sync(0xffffffffu, a2.w, 16);
    a3.x += __shfl_xor_sync(0xffffffffu, a3.x, 16); a3.y += __shfl_xor_sync(0xffffffffu, a3.y, 16);
    a3.z += __shfl_xor_sync(0xffffffffu, a3.z, 16); a3.w += __shfl_xor_sync(0xffffffffu, a3.w, 16);
    a4.x += __shfl_xor_sync(0xffffffffu, a4.x, 16); a4.y += __shfl_xor_sync(0xffffffffu, a4.y, 16);
    a4.z += __shfl_xor_sync(0xffffffffu, a4.z, 16); a4.w += __shfl_xor_sync(0xffffffffu, a4.w, 16);
    if (half == 0) {
        int p0 = 4 * sub;
        atomicAdd(&red[p0 + 0], a0.x); atomicAdd(&red[p0 + 1], a0.y);
        atomicAdd(&red[p0 + 2], a0.z); atomicAdd(&red[p0 + 3], a0.w);
        int p1 = 4 * (sub + 16);
        atomicAdd(&red[p1 + 0], a1.x); atomicAdd(&red[p1 + 1], a1.y);
        atomicAdd(&red[p1 + 2], a1.z); atomicAdd(&red[p1 + 3], a1.w);
        int p2 = 4 * (sub + 32);
        atomicAdd(&red[p2 + 0], a2.x); atomicAdd(&red[p2 + 1], a2.y);
        atomicAdd(&red[p2 + 2], a2.z); atomicAdd(&red[p2 + 3], a2.w);
        int p3 = 4 * (sub + 48);
        atomicAdd(&red[p3 + 0], a3.x); atomicAdd(&red[p3 + 1], a3.y);
        atomicAdd(&red[p3 + 2], a3.z); atomicAdd(&red[p3 + 3], a3.w);
        if (sub < 11) {
            int p4 = 4 * (sub + 64);
            atomicAdd(&red[p4 + 0], a4.x); atomicAdd(&red[p4 + 1], a4.y);
            atomicAdd(&red[p4 + 2], a4.z); atomicAdd(&red[p4 + 3], a4.w);
        }
    }
    __syncthreads();
    if (tid < D_) g_matt[b * D_ + tid] = red[tid];
}

// ---------------- head phase: 1 row x 1 float4 per thread, deep unroll ----------
// (proven arithmetic, untouched)
__device__ __forceinline__ void phase1r(const float* __restrict__ W,
                                        const float* __restrict__ bias,
                                        const float* __restrict__ x,
                                        float* __restrict__ y,
                                        int jc, bool dotanh) {
    if (jc >= 75) return;
    const float4* W4 = reinterpret_cast<const float4*>(W);
    float4 acc = reinterpret_cast<const float4*>(bias)[jc];
#pragma unroll 12
    for (int d = 0; d < D_; d++) {
        float4 w = W4[d * 75 + jc];
        float a = x[d];
        acc.x = fmaf(a, w.x, acc.x); acc.y = fmaf(a, w.y, acc.y);
        acc.z = fmaf(a, w.z, acc.z); acc.w = fmaf(a, w.w, acc.w);
    }
    if (dotanh) {
        acc.x = tanhf(acc.x); acc.y = tanhf(acc.y);
        acc.z = tanhf(acc.z); acc.w = tanhf(acc.w);
    }
    reinterpret_cast<float4*>(y)[jc] = acc;
}

// ---------------- head: 32 blocks x 640 threads, R=8 rows/block ----------------
// (same per-thread arithmetic as proven R=2 version; only the grid shape changes
//  to get 20 warps/block for latency hiding)
__global__ void __launch_bounds__(640, 1)
head_kernel(const float* __restrict__ Wk, const float* __restrict__ bk,
            const float* __restrict__ Wproj, const float* __restrict__ bproj,
            const float* __restrict__ Wm, const float* __restrict__ bm,
            const float* __restrict__ Wd, const float* __restrict__ bd,
            float* __restrict__ out) {
    const int R = 8;
    int b0 = blockIdx.x * R, tid = threadIdx.x;
    int jc = tid % 80, r = tid / 80;      // r in 0..7
    int warp = tid >> 5, lane = tid & 31; // 20 warps
    __shared__ float sA[R * D_];
    __shared__ float sB[R * D_];
    __shared__ float slog[R][P_];

    for (int i = tid; i < R * D_; i += 640) sA[i] = g_matt[b0 * D_ + i];
    __syncthreads();

    phase1r(Wk, bk, sA + r * D_, sB + r * D_, jc, false);
    __syncthreads();
    phase1r(Wproj, bproj, sB + r * D_, sA + r * D_, jc, false);
    __syncthreads();
    for (int i = tid; i < R * D_; i += 640) {
        int rr = i / D_;
        sA[i] += g_sumvec[b0 * D_ + i] / (float)g_len[(b0 + rr) * 3 + 0];
    }
    __syncthreads();
    phase1r(Wm, bm, sA + r * D_, sB + r * D_, jc, true);
    __syncthreads();

    // logits: 24 (r,p) pairs over 20 warps
    for (int idx = warp; idx < R * P_; idx += 20) {
        int rr = idx / P_, p = idx % P_;
        const float* row = sB + rr * D_;
        float s = 0.f;
#pragma unroll
        for (int k = 0; k < 9; k++) {
            int j = lane + 32 * k;
            s = fmaf(row[j], Wd[j * P_ + p], s);
        }
        if (lane < 12) {
            int j = 288 + lane;
            s = fmaf(row[j], Wd[j * P_ + p], s);
        }
#pragma unroll
        for (int off = 16; off; off >>= 1) s += __shfl_xor_sync(0xffffffffu, s, off);
        if (lane == 0) slog[rr][p] = s + bd[p];
    }
    __syncthreads();
    if (tid < R) {
        int rr = tid;
        float m = fmaxf(slog[rr][0], fmaxf(slog[rr][1], slog[rr][2]));
        float e0 = expf(slog[rr][0] - m), e1 = expf(slog[rr][1] - m), e2 = expf(slog[rr][2] - m);
        float inv = 1.f / (e0 + e1 + e2);
        out[(b0 + rr) * P_ + 0] = e0 * inv;
        out[(b0 + rr) * P_ + 1] = e1 * inv;
        out[(b0 + rr) * P_ + 2] = e2 * inv;
    }
}

extern "C" void kernel_launch(void* const* d_in, const int* in_sizes, int n_in,
                              void* d_out, int out_size) {
    const int*   text   = (const int*)d_in[0];
    const int*   aspect = (const int*)d_in[1];
    const int*   left   = (const int*)d_in[2];
    const float* embed  = (const float*)d_in[3];
    const float* Wx     = (const float*)d_in[4];
    // d_in[5] = Ws (dead in reference)
    const float* Wk     = (const float*)d_in[6];
    const float* bk     = (const float*)d_in[7];
    const float* Wq     = (const float*)d_in[8];
    const float* bq     = (const float*)d_in[9];
    const float* w_mlp  = (const float*)d_in[10];
    const float* Wproj  = (const float*)d_in[11];
    const float* bproj  = (const float*)d_in[12];
    const float* Wm     = (const float*)d_in[13];
    const float* bm     = (const float*)d_in[14];
    const float* Wd     = (const float*)d_in[15];
    const float* bd     = (const float*)d_in[16];
    float* out = (float*)d_out;

    combo_kernel<<<287, 320>>>(text, aspect, left, embed, Wk, bk, Wq, bq, w_mlp);
    mv_kernel<<<30, 320>>>(Wx, 0);
    mv_kernel<<<30, 320>>>(Wx, 1);
    mv_kernel<<<30, 320>>>(Wx, 2);
    fused_kernel<<<B_, 512>>>(text, (const float4*)embed);
    head_kernel<<<B_ / 8, 640>>>(Wk, bk, Wproj, bproj, Wm, bm, Wd, bd, out);
}

// round 15
// speedup vs baseline: 1.1080x; 1.1080x over previous
#include <cuda_runtime.h>
#include <cstdint>

#define B_   256
#define L_   512
#define LA_  8
#define LLF_ 64
#define V_   100000
#define D_   300
#define P_   3
#define D4_  75

// ---------------- device scratch ----------------
__device__ __align__(16) float g_asp_e[B_ * D_];
__device__ __align__(16) float g_sumvec[B_ * D_];
__device__ __align__(16) float g_matt[B_ * D_];
__device__ int   g_len[B_ * 3];
__device__ __align__(16) float g_u[D_];
__device__ __align__(16) float g_v[D_];
__device__ __align__(16) float g_t1[D_];
__device__ __align__(16) float g_t2[D_];
__device__ __align__(16) float g_wv[D_];
__device__ float g_sc[2];

// ---------------- combo: blocks 0..30 vec-part, blocks 31..286 prep-part --------
__global__ void combo_kernel(const int* __restrict__ text,
                             const int* __restrict__ aspect,
                             const int* __restrict__ left,
                             const float* __restrict__ embed,
                             const float* __restrict__ Wk,
                             const float* __restrict__ bk,
                             const float* __restrict__ Wq,
                             const float* __restrict__ bq,
                             const float* __restrict__ w_mlp) {
    int tid = threadIdx.x;
    if (blockIdx.x < 31) {
        int warp = tid >> 5, lane = tid & 31;
        int gw = blockIdx.x * 10 + warp;
        if (gw < D_) {
            float u = 0.f, q = 0.f;
            int base = gw * D_;
#pragma unroll
            for (int k = 0; k < 9; k++) {
                int j = lane + 32 * k;
                u = fmaf(Wk[base + j], w_mlp[j], u);
                q = fmaf(Wq[base + j], w_mlp[D_ + j], q);
            }
            if (lane < 12) {
                int j = 288 + lane;
                u = fmaf(Wk[base + j], w_mlp[j], u);
                q = fmaf(Wq[base + j], w_mlp[D_ + j], q);
            }
#pragma unroll
            for (int off = 16; off; off >>= 1) {
                u += __shfl_xor_sync(0xffffffffu, u, off);
                q += __shfl_xor_sync(0xffffffffu, q, off);
            }
            if (lane == 0) { g_u[gw] = u; g_v[gw] = q; }
        } else if (gw == D_ || gw == D_ + 1) {
            const float* v1 = (gw == D_) ? bk : bq;
            const float* v2 = (gw == D_) ? w_mlp : (w_mlp + D_);
            float s = 0.f;
            for (int j = lane; j < D_; j += 32) s = fmaf(v1[j], v2[j], s);
#pragma unroll
            for (int off = 16; off; off >>= 1) s += __shfl_xor_sync(0xffffffffu, s, off);
            if (lane == 0) g_sc[gw - D_] = s;
        }
    } else {
        int b = blockIdx.x - 31;
        __shared__ int cnt[3];
        if (tid < 3) cnt[tid] = 0;
        __syncthreads();
        int c0 = 0;
        for (int l = tid; l < L_; l += 320) c0 += (text[b * L_ + l] != 0);
        int c1 = (tid < LA_) ? (aspect[b * LA_ + tid] != 0) : 0;
        int c2 = 0;
        for (int l = tid; l < LLF_; l += 320) c2 += (left[b * LLF_ + l] != 0);
        if (c0) atomicAdd(&cnt[0], c0);
        if (c1) atomicAdd(&cnt[1], c1);
        if (c2) atomicAdd(&cnt[2], c2);
        __syncthreads();
        if (tid < 3) g_len[b * 3 + tid] = cnt[tid];
        if (tid < D_) {
            float s = 0.f;
#pragma unroll
            for (int j = 0; j < LA_; j++) {
                int tok = aspect[b * LA_ + j];
                s += embed[(long)tok * D_ + tid];
            }
            g_asp_e[b * D_ + tid] = s / (float)cnt[1];
        }
    }
}

// ---------------- mv: out = Wx @ in (warp per row, wide grid) ----------------
__global__ void mv_kernel(const float* __restrict__ Wx, int step) {
    const float* in  = (step == 0) ? g_v : ((step == 1) ? g_t1 : g_t2);
    float*       out = (step == 0) ? g_t1 : ((step == 1) ? g_t2 : g_wv);
    int warp = threadIdx.x >> 5, lane = threadIdx.x & 31;
    int row = blockIdx.x * 10 + warp;
    if (row >= D_) return;
    int base = row * D_;
    float s = 0.f;
#pragma unroll
    for (int k = 0; k < 9; k++) {
        int j = lane + 32 * k;
        s = fmaf(Wx[base + j], in[j], s);
    }
    if (lane < 12) s = fmaf(Wx[base + 288 + lane], in[288 + lane], s);
#pragma unroll
    for (int off = 16; off; off >>= 1) s += __shfl_xor_sync(0xffffffffu, s, off);
    if (lane == 0) out[row] = s;
}

// ---------------- fused: qs-dot + dots + raw sum + softmax + weighted gather ----
// (round-8/11 proven version: inline shfl dot reduction)
__global__ void __launch_bounds__(512, 2)
fused_kernel(const int* __restrict__ text, const float4* __restrict__ embed4) {
    __shared__ float4 su[D4_ + 1];
    __shared__ float red[D_];
    __shared__ float sc[L_];
    __shared__ int   tok_s[L_];
    __shared__ float rbuf[20];
    int tid = threadIdx.x, b = blockIdx.x;
    int warp = tid >> 5, lane = tid & 31;

    if (tid < D4_) su[tid] = reinterpret_cast<const float4*>(g_u)[tid];
    if (tid == D4_) su[D4_] = make_float4(0.f, 0.f, 0.f, 0.f);
    if (tid < D_) red[tid] = 0.f;
    tok_s[tid] = text[b * L_ + tid];
    // warp 0: qs = asp_e[b] · g_wv
    if (warp == 0) {
        float s = 0.f;
        int base = b * D_;
#pragma unroll
        for (int k = 0; k < 9; k++) {
            int j = lane + 32 * k;
            s = fmaf(g_asp_e[base + j], g_wv[j], s);
        }
        if (lane < 12) s = fmaf(g_asp_e[base + 288 + lane], g_wv[288 + lane], s);
#pragma unroll
        for (int off = 16; off; off >>= 1) s += __shfl_xor_sync(0xffffffffu, s, off);
        if (lane == 0) rbuf[18] = s;
    }
    __syncthreads();

    float memf  = (float)g_len[b * 3 + 0];
    float start = (float)(g_len[b * 3 + 2] - g_len[b * 3 + 1]);
    float endf  = (float)g_len[b * 3 + 2];
    float qs = rbuf[18] + g_sc[1];
    float cc = g_sc[0];
    float inv_memf = 1.f / memf;

    int half = lane >> 4, sub = lane & 15;
    int l0 = warp * 32;
    int last = (sub < 11) ? (sub + 64) : (D4_ - 1);

    float4 u0 = su[sub], u1 = su[sub + 16], u2 = su[sub + 32], u3 = su[sub + 48];
    float4 u4 = (sub < 11) ? su[sub + 64] : make_float4(0.f, 0.f, 0.f, 0.f);

    float4 a0 = make_float4(0.f,0.f,0.f,0.f), a1 = a0, a2 = a0, a3 = a0, a4 = a0;

    // ---- phase 1: dots (inline reduce) + raw sum ----
#pragma unroll 4
    for (int it = 0; it < 16; it++) {
        int l = l0 + 2 * it + half;
        int tok = tok_s[l];
        const float4* row = embed4 + (long)tok * D4_;
        float4 v0 = row[sub];
        float4 v1 = row[sub + 16];
        float4 v2 = row[sub + 32];
        float4 v3 = row[sub + 48];
        float4 v4 = row[last];
        if (sub >= 11) v4 = make_float4(0.f, 0.f, 0.f, 0.f);

        float d = v0.x*u0.x + v0.y*u0.y + v0.z*u0.z + v0.w*u0.w
                + v1.x*u1.x + v1.y*u1.y + v1.z*u1.z + v1.w*u1.w
                + v2.x*u2.x + v2.y*u2.y + v2.z*u2.z + v2.w*u2.w
                + v3.x*u3.x + v3.y*u3.y + v3.z*u3.z + v3.w*u3.w
                + v4.x*u4.x + v4.y*u4.y + v4.z*u4.z + v4.w*u4.w;

        a0.x += v0.x; a0.y += v0.y; a0.z += v0.z; a0.w += v0.w;
        a1.x += v1.x; a1.y += v1.y; a1.z += v1.z; a1.w += v1.w;
        a2.x += v2.x; a2.y += v2.y; a2.z += v2.z; a2.w += v2.w;
        a3.x += v3.x; a3.y += v3.y; a3.z += v3.z; a3.w += v3.w;
        a4.x += v4.x; a4.y += v4.y; a4.z += v4.z; a4.w += v4.w;

#pragma unroll
        for (int off = 8; off; off >>= 1) d += __shfl_xor_sync(0xffffffffu, d, off);
        if (sub == 0) sc[l] = d;
    }
    a0.x += __shfl_xor_sync(0xffffffffu, a0.x, 16); a0.y += __shfl_xor_sync(0xffffffffu, a0.y, 16);
    a0.z += __shfl_xor_sync(0xffffffffu, a0.z, 16); a0.w += __shfl_xor_sync(0xffffffffu, a0.w, 16);
    a1.x += __shfl_xor_sync(0xffffffffu, a1.x, 16); a1.y += __shfl_xor_sync(0xffffffffu, a1.y, 16);
    a1.z += __shfl_xor_sync(0xffffffffu, a1.z, 16); a1.w += __shfl_xor_sync(0xffffffffu, a1.w, 16);
    a2.x += __shfl_xor_sync(0xffffffffu, a2.x, 16); a2.y += __shfl_xor_sync(0xffffffffu, a2.y, 16);
    a2.z += __shfl_xor_sync(0xffffffffu, a2.z, 16); a2.w += __shfl_xor_sync(0xffffffffu, a2.w, 16);
    a3.x += __shfl_xor_sync(0xffffffffu, a3.x, 16); a3.y += __shfl_xor_sync(0xffffffffu, a3.y, 16);
    a3.z += __shfl_xor_sync(0xffffffffu, a3.z, 16); a3.w += __shfl_xor_sync(0xffffffffu, a3.w, 16);
    a4.x += __shfl_xor_sync(0xffffffffu, a4.x, 16); a4.y += __shfl_xor_sync(0xffffffffu, a4.y, 16);
    a4.z += __shfl_xor_sync(0xffffffffu, a4.z, 16); a4.w += __shfl_xor_sync(0xffffffffu, a4.w, 16);
    if (half == 0) {
        int p0 = 4 * sub;
        atomicAdd(&red[p0 + 0], a0.x); atomicAdd(&red[p0 + 1], a0.y);
        atomicAdd(&red[p0 + 2], a0.z); atomicAdd(&red[p0 + 3], a0.w);
        int p1 = 4 * (sub + 16);
        atomicAdd(&red[p1 + 0], a1.x); atomicAdd(&red[p1 + 1], a1.y);
        atomicAdd(&red[p1 + 2], a1.z); atomicAdd(&red[p1 + 3], a1.w);
        int p2 = 4 * (sub + 32);
        atomicAdd(&red[p2 + 0], a2.x); atomicAdd(&red[p2 + 1], a2.y);
        atomicAdd(&red[p2 + 2], a2.z); atomicAdd(&red[p2 + 3], a2.w);
        int p3 = 4 * (sub + 48);
        atomicAdd(&red[p3 + 0], a3.x); atomicAdd(&red[p3 + 1], a3.y);
        atomicAdd(&red[p3 + 2], a3.z); atomicAdd(&red[p3 + 3], a3.w);
        if (sub < 11) {
            int p4 = 4 * (sub + 64);
            atomicAdd(&red[p4 + 0], a4.x); atomicAdd(&red[p4 + 1], a4.y);
            atomicAdd(&red[p4 + 2], a4.z); atomicAdd(&red[p4 + 3], a4.w);
        }
    }
    __syncthreads();
    if (tid < D_) { g_sumvec[b * D_ + tid] = red[tid]; red[tid] = 0.f; }

    // ---- softmax over L in-block ----
    float idx = (float)tid;
    float lv = idx < start ? (start - idx) : (idx <= endf ? 0.f : idx - endf);
    float wv = 1.f - lv * inv_memf;
    if (!(idx < memf)) wv = 0.f;
    float logit = tanhf(sc[tid] * wv + cc + qs);

    float m = logit;
#pragma unroll
    for (int off = 16; off; off >>= 1) m = fmaxf(m, __shfl_xor_sync(0xffffffffu, m, off));
    if (lane == 0) rbuf[warp] = m;
    __syncthreads();
    if (warp == 0) {
        float mm = (lane < 16) ? rbuf[lane] : -1e30f;
#pragma unroll
        for (int off = 16; off; off >>= 1) mm = fmaxf(mm, __shfl_xor_sync(0xffffffffu, mm, off));
        if (lane == 0) rbuf[16] = mm;
    }
    __syncthreads();
    m = rbuf[16];
    float e = expf(logit - m);
    float s = e;
#pragma unroll
    for (int off = 16; off; off >>= 1) s += __shfl_xor_sync(0xffffffffu, s, off);
    if (lane == 0) rbuf[warp] = s;
    __syncthreads();
    if (warp == 0) {
        float ss = (lane < 16) ? rbuf[lane] : 0.f;
#pragma unroll
        for (int off = 16; off; off >>= 1) ss += __shfl_xor_sync(0xffffffffu, ss, off);
        if (lane == 0) rbuf[17] = ss;
    }
    __syncthreads();
    float inv = 1.f / rbuf[17];
    sc[tid] = e * inv * wv;
    __syncthreads();

    // ---- phase 2: weighted gather (rows hot in L1/L2) ----
    a0 = make_float4(0.f,0.f,0.f,0.f); a1 = a0; a2 = a0; a3 = a0; a4 = a0;
#pragma unroll 4
    for (int it = 0; it < 16; it++) {
        int l = l0 + 2 * it + half;
        float swv = sc[l];
        if (swv != 0.f) {
            int tok = tok_s[l];
            const float4* row = embed4 + (long)tok * D4_;
            float4 v0 = row[sub];
            float4 v1 = row[sub + 16];
            float4 v2 = row[sub + 32];
            float4 v3 = row[sub + 48];
            float4 v4 = row[last];
            a0.x = fmaf(swv, v0.x, a0.x); a0.y = fmaf(swv, v0.y, a0.y);
            a0.z = fmaf(swv, v0.z, a0.z); a0.w = fmaf(swv, v0.w, a0.w);
            a1.x = fmaf(swv, v1.x, a1.x); a1.y = fmaf(swv, v1.y, a1.y);
            a1.z = fmaf(swv, v1.z, a1.z); a1.w = fmaf(swv, v1.w, a1.w);
            a2.x = fmaf(swv, v2.x, a2.x); a2.y = fmaf(swv, v2.y, a2.y);
            a2.z = fmaf(swv, v2.z, a2.z); a2.w = fmaf(swv, v2.w, a2.w);
            a3.x = fmaf(swv, v3.x, a3.x); a3.y = fmaf(swv, v3.y, a3.y);
            a3.z = fmaf(swv, v3.z, a3.z); a3.w = fmaf(swv, v3.w, a3.w);
            if (sub < 11) {
                a4.x = fmaf(swv, v4.x, a4.x); a4.y = fmaf(swv, v4.y, a4.y);
                a4.z = fmaf(swv, v4.z, a4.z); a4.w = fmaf(swv, v4.w, a4.w);
            }
        }
    }
    a0.x += __shfl_xor_sync(0xffffffffu, a0.x, 16); a0.y += __shfl_xor_sync(0xffffffffu, a0.y, 16);
    a0.z += __shfl_xor_sync(0xffffffffu, a0.z, 16); a0.w += __shfl_xor_sync(0xffffffffu, a0.w, 16);
    a1.x += __shfl_xor_sync(0xffffffffu, a1.x, 16); a1.y += __shfl_xor_sync(0xffffffffu, a1.y, 16);
    a1.z += __shfl_xor_sync(0xffffffffu, a1.z, 16); a1.w += __shfl_xor_sync(0xffffffffu, a1.w, 16);
    a2.x += __shfl_xor_sync(0xffffffffu, a2.x, 16); a2.y += __shfl_xor_sync(0xffffffffu, a2.y, 16);
    a2.z += __shfl_xor_sync(0xffffffffu, a2.z, 16); a2.w += __shfl_xor_sync(0xffffffffu, a2.w, 16);
    a3.x += __shfl_xor_sync(0xffffffffu, a3.x, 16); a3.y += __shfl_xor_sync(0xffffffffu, a3.y, 16);
    a3.z += __shfl_xor_sync(0xffffffffu, a3.z, 16); a3.w += __shfl_xor_sync(0xffffffffu, a3.w, 16);
    a4.x += __shfl_xor_sync(0xffffffffu, a4.x, 16); a4.y += __shfl_xor_sync(0xffffffffu, a4.y, 16);
    a4.z += __shfl_xor_sync(0xffffffffu, a4.z, 16); a4.w += __shfl_xor_sync(0xffffffffu, a4.w, 16);
    if (half == 0) {
        int p0 = 4 * sub;
        atomicAdd(&red[p0 + 0], a0.x); atomicAdd(&red[p0 + 1], a0.y);
        atomicAdd(&red[p0 + 2], a0.z); atomicAdd(&red[p0 + 3], a0.w);
        int p1 = 4 * (sub + 16);
        atomicAdd(&red[p1 + 0], a1.x); atomicAdd(&red[p1 + 1], a1.y);
        atomicAdd(&red[p1 + 2], a1.z); atomicAdd(&red[p1 + 3], a1.w);
        int p2 = 4 * (sub + 32);
        atomicAdd(&red[p2 + 0], a2.x); atomicAdd(&red[p2 + 1], a2.y);
        atomicAdd(&red[p2 + 2], a2.z); atomicAdd(&red[p2 + 3], a2.w);
        int p3 = 4 * (sub + 48);
        atomicAdd(&red[p3 + 0], a3.x); atomicAdd(&red[p3 + 1], a3.y);
        atomicAdd(&red[p3 + 2], a3.z); atomicAdd(&red[p3 + 3], a3.w);
        if (sub < 11) {
            int p4 = 4 * (sub + 64);
            atomicAdd(&red[p4 + 0], a4.x); atomicAdd(&red[p4 + 1], a4.y);
            atomicAdd(&red[p4 + 2], a4.z); atomicAdd(&red[p4 + 3], a4.w);
        }
    }
    __syncthreads();
    if (tid < D_) g_matt[b * D_ + tid] = red[tid];
}

// ---------------- head phase: paired-thread split-d, shuffle combine ------------
// thread pair (tid, tid^1) owns (r, jc); dh = tid&1 selects d-half of 150.
// Combine via __shfl_xor_sync(.., 1) — same warp always, no smem scratch.
__device__ __forceinline__ void phaseP(const float* __restrict__ W,
                                       const float* __restrict__ bias,
                                       const float* __restrict__ x,
                                       float* __restrict__ y,
                                       int k, int dh, int r, int jc,
                                       bool dotanh) {
    float4 acc = make_float4(0.f, 0.f, 0.f, 0.f);
    if (k < 300) {
        const float4* W4 = reinterpret_cast<const float4*>(W);
        const float* xr = x + r * D_;
        int d0 = dh * 150;
#pragma unroll 10
        for (int d = d0; d < d0 + 150; d++) {
            float4 w = W4[d * 75 + jc];
            float a = xr[d];
            acc.x = fmaf(a, w.x, acc.x); acc.y = fmaf(a, w.y, acc.y);
            acc.z = fmaf(a, w.z, acc.z); acc.w = fmaf(a, w.w, acc.w);
        }
    }
    acc.x += __shfl_xor_sync(0xffffffffu, acc.x, 1);
    acc.y += __shfl_xor_sync(0xffffffffu, acc.y, 1);
    acc.z += __shfl_xor_sync(0xffffffffu, acc.z, 1);
    acc.w += __shfl_xor_sync(0xffffffffu, acc.w, 1);
    if (k < 300 && dh == 0) {
        float4 b4 = reinterpret_cast<const float4*>(bias)[jc];
        acc.x += b4.x; acc.y += b4.y; acc.z += b4.z; acc.w += b4.w;
        if (dotanh) {
            acc.x = tanhf(acc.x); acc.y = tanhf(acc.y);
            acc.z = tanhf(acc.z); acc.w = tanhf(acc.w);
        }
        reinterpret_cast<float4*>(y + r * D_)[jc] = acc;
    }
    __syncthreads();
}

// ---------------- head: 64 blocks x 640 threads, R=4, paired split-d -----------
__global__ void __launch_bounds__(640, 1)
head_kernel(const float* __restrict__ Wk, const float* __restrict__ bk,
            const float* __restrict__ Wproj, const float* __restrict__ bproj,
            const float* __restrict__ Wm, const float* __restrict__ bm,
            const float* __restrict__ Wd, const float* __restrict__ bd,
            float* __restrict__ out) {
    const int R = 4;
    int b0 = blockIdx.x * R, tid = threadIdx.x;
    int k = tid >> 1, dh = tid & 1;      // pair index, d-half
    int r = k / 75, jc = k % 75;         // valid when k < 300
    int warp = tid >> 5, lane = tid & 31;
    __shared__ __align__(16) float sA[R * D_];
    __shared__ __align__(16) float sB[R * D_];
    __shared__ float slog[R][P_];

    for (int i = tid; i < R * D_; i += 640) sA[i] = g_matt[b0 * D_ + i];
    __syncthreads();

    phaseP(Wk, bk, sA, sB, k, dh, r, jc, false);
    phaseP(Wproj, bproj, sB, sA, k, dh, r, jc, false);
    for (int i = tid; i < R * D_; i += 640) {
        int rr = i / D_;
        sA[i] += g_sumvec[b0 * D_ + i] / (float)g_len[(b0 + rr) * 3 + 0];
    }
    __syncthreads();
    phaseP(Wm, bm, sA, sB, k, dh, r, jc, true);

    // logits: 12 (r,p) pairs over 20 warps
    for (int idx = warp; idx < R * P_; idx += 20) {
        int rr = idx / P_, p = idx % P_;
        const float* row = sB + rr * D_;
        float s = 0.f;
#pragma unroll
        for (int kk = 0; kk < 9; kk++) {
            int j = lane + 32 * kk;
            s = fmaf(row[j], Wd[j * P_ + p], s);
        }
        if (lane < 12) {
            int j = 288 + lane;
            s = fmaf(row[j], Wd[j * P_ + p], s);
        }
#pragma unroll
        for (int off = 16; off; off >>= 1) s += __shfl_xor_sync(0xffffffffu, s, off);
        if (lane == 0) slog[rr][p] = s + bd[p];
    }
    __syncthreads();
    if (tid < R) {
        int rr = tid;
        float m = fmaxf(slog[rr][0], fmaxf(slog[rr][1], slog[rr][2]));
        float e0 = expf(slog[rr][0] - m), e1 = expf(slog[rr][1] - m), e2 = expf(slog[rr][2] - m);
        float inv = 1.f / (e0 + e1 + e2);
        out[(b0 + rr) * P_ + 0] = e0 * inv;
        out[(b0 + rr) * P_ + 1] = e1 * inv;
        out[(b0 + rr) * P_ + 2] = e2 * inv;
    }
}

extern "C" void kernel_launch(void* const* d_in, const int* in_sizes, int n_in,
                              void* d_out, int out_size) {
    const int*   text   = (const int*)d_in[0];
    const int*   aspect = (const int*)d_in[1];
    const int*   left   = (const int*)d_in[2];
    const float* embed  = (const float*)d_in[3];
    const float* Wx     = (const float*)d_in[4];
    // d_in[5] = Ws (dead in reference)
    const float* Wk     = (const float*)d_in[6];
    const float* bk     = (const float*)d_in[7];
    const float* Wq     = (const float*)d_in[8];
    const float* bq     = (const float*)d_in[9];
    const float* w_mlp  = (const float*)d_in[10];
    const float* Wproj  = (const float*)d_in[11];
    const float* bproj  = (const float*)d_in[12];
    const float* Wm     = (const float*)d_in[13];
    const float* bm     = (const float*)d_in[14];
    const float* Wd     = (const float*)d_in[15];
    const float* bd     = (const float*)d_in[16];
    float* out = (float*)d_out;

    combo_kernel<<<287, 320>>>(text, aspect, left, embed, Wk, bk, Wq, bq, w_mlp);
    mv_kernel<<<30, 320>>>(Wx, 0);
    mv_kernel<<<30, 320>>>(Wx, 1);
    mv_kernel<<<30, 320>>>(Wx, 2);
    fused_kernel<<<B_, 512>>>(text, (const float4*)embed);
    head_kernel<<<B_ / 4, 640>>>(Wk, bk, Wproj, bproj, Wm, bm, Wd, bd, out);
}

// round 16
// speedup vs baseline: 1.2666x; 1.1432x over previous
#include <cuda_runtime.h>
#include <cstdint>

#define B_   256
#define L_   512
#define LA_  8
#define LLF_ 64
#define V_   100000
#define D_   300
#define P_   3
#define D4_  75

// ---------------- device scratch ----------------
__device__ __align__(16) float g_asp_e[B_ * D_];
__device__ __align__(16) float g_sumvec[B_ * D_];
__device__ __align__(16) float g_matt[B_ * D_];
__device__ int   g_len[B_ * 3];
__device__ __align__(16) float g_u[D_];
__device__ __align__(16) float g_v[D_];
__device__ __align__(16) float g_t1[D_];
__device__ __align__(16) float g_t2[D_];
__device__ __align__(16) float g_wv[D_];
__device__ float g_sc[2];

// ---------------- combo: blocks 0..30 vec-part, blocks 31..286 prep-part --------
__global__ void combo_kernel(const int* __restrict__ text,
                             const int* __restrict__ aspect,
                             const int* __restrict__ left,
                             const float* __restrict__ embed,
                             const float* __restrict__ Wk,
                             const float* __restrict__ bk,
                             const float* __restrict__ Wq,
                             const float* __restrict__ bq,
                             const float* __restrict__ w_mlp) {
    int tid = threadIdx.x;
    if (blockIdx.x < 31) {
        int warp = tid >> 5, lane = tid & 31;
        int gw = blockIdx.x * 10 + warp;
        if (gw < D_) {
            float u = 0.f, q = 0.f;
            int base = gw * D_;
#pragma unroll
            for (int k = 0; k < 9; k++) {
                int j = lane + 32 * k;
                u = fmaf(Wk[base + j], w_mlp[j], u);
                q = fmaf(Wq[base + j], w_mlp[D_ + j], q);
            }
            if (lane < 12) {
                int j = 288 + lane;
                u = fmaf(Wk[base + j], w_mlp[j], u);
                q = fmaf(Wq[base + j], w_mlp[D_ + j], q);
            }
#pragma unroll
            for (int off = 16; off; off >>= 1) {
                u += __shfl_xor_sync(0xffffffffu, u, off);
                q += __shfl_xor_sync(0xffffffffu, q, off);
            }
            if (lane == 0) { g_u[gw] = u; g_v[gw] = q; }
        } else if (gw == D_ || gw == D_ + 1) {
            const float* v1 = (gw == D_) ? bk : bq;
            const float* v2 = (gw == D_) ? w_mlp : (w_mlp + D_);
            float s = 0.f;
            for (int j = lane; j < D_; j += 32) s = fmaf(v1[j], v2[j], s);
#pragma unroll
            for (int off = 16; off; off >>= 1) s += __shfl_xor_sync(0xffffffffu, s, off);
            if (lane == 0) g_sc[gw - D_] = s;
        }
    } else {
        int b = blockIdx.x - 31;
        __shared__ int cnt[3];
        if (tid < 3) cnt[tid] = 0;
        __syncthreads();
        int c0 = 0;
        for (int l = tid; l < L_; l += 320) c0 += (text[b * L_ + l] != 0);
        int c1 = (tid < LA_) ? (aspect[b * LA_ + tid] != 0) : 0;
        int c2 = 0;
        for (int l = tid; l < LLF_; l += 320) c2 += (left[b * LLF_ + l] != 0);
        if (c0) atomicAdd(&cnt[0], c0);
        if (c1) atomicAdd(&cnt[1], c1);
        if (c2) atomicAdd(&cnt[2], c2);
        __syncthreads();
        if (tid < 3) g_len[b * 3 + tid] = cnt[tid];
        if (tid < D_) {
            float s = 0.f;
#pragma unroll
            for (int j = 0; j < LA_; j++) {
                int tok = aspect[b * LA_ + j];
                s += embed[(long)tok * D_ + tid];
            }
            g_asp_e[b * D_ + tid] = s / (float)cnt[1];
        }
    }
}

// ---------------- mv: out = Wx @ in (warp per row, wide grid) ----------------
__global__ void mv_kernel(const float* __restrict__ Wx, int step) {
    const float* in  = (step == 0) ? g_v : ((step == 1) ? g_t1 : g_t2);
    float*       out = (step == 0) ? g_t1 : ((step == 1) ? g_t2 : g_wv);
    int warp = threadIdx.x >> 5, lane = threadIdx.x & 31;
    int row = blockIdx.x * 10 + warp;
    if (row >= D_) return;
    int base = row * D_;
    float s = 0.f;
#pragma unroll
    for (int k = 0; k < 9; k++) {
        int j = lane + 32 * k;
        s = fmaf(Wx[base + j], in[j], s);
    }
    if (lane < 12) s = fmaf(Wx[base + 288 + lane], in[288 + lane], s);
#pragma unroll
    for (int off = 16; off; off >>= 1) s += __shfl_xor_sync(0xffffffffu, s, off);
    if (lane == 0) out[row] = s;
}

// ---------------- fused: ONE PASS — dots + online (maxless) softmax-weighted sum
// tanh bounds logits to (-1,1) so exp() needs no max subtraction.
__global__ void __launch_bounds__(512)
fused_kernel(const int* __restrict__ text, const float4* __restrict__ embed4) {
    __shared__ float4 su[D4_ + 1];
    __shared__ float red[D_];     // raw row sum
    __shared__ float red2[D_];    // sum of e*wv*row
    __shared__ int   tok_s[L_];
    __shared__ float rbuf[2];
    __shared__ float sden;
    int tid = threadIdx.x, b = blockIdx.x;
    int warp = tid >> 5, lane = tid & 31;

    if (tid < D4_) su[tid] = reinterpret_cast<const float4*>(g_u)[tid];
    if (tid == D4_) su[D4_] = make_float4(0.f, 0.f, 0.f, 0.f);
    if (tid < D_) { red[tid] = 0.f; red2[tid] = 0.f; }
    if (tid == 511) sden = 0.f;
    tok_s[tid] = text[b * L_ + tid];
    // warp 0: qs = asp_e[b] · g_wv
    if (warp == 0) {
        float s = 0.f;
        int base = b * D_;
#pragma unroll
        for (int k = 0; k < 9; k++) {
            int j = lane + 32 * k;
            s = fmaf(g_asp_e[base + j], g_wv[j], s);
        }
        if (lane < 12) s = fmaf(g_asp_e[base + 288 + lane], g_wv[288 + lane], s);
#pragma unroll
        for (int off = 16; off; off >>= 1) s += __shfl_xor_sync(0xffffffffu, s, off);
        if (lane == 0) rbuf[0] = s;
    }
    __syncthreads();

    float memf  = (float)g_len[b * 3 + 0];
    float start = (float)(g_len[b * 3 + 2] - g_len[b * 3 + 1]);
    float endf  = (float)g_len[b * 3 + 2];
    float cq = rbuf[0] + g_sc[1] + g_sc[0];   // cc + qs combined
    float inv_memf = 1.f / memf;

    int half = lane >> 4, sub = lane & 15;
    int l0 = warp * 32;
    int last = (sub < 11) ? (sub + 64) : (D4_ - 1);

    float4 u0 = su[sub], u1 = su[sub + 16], u2 = su[sub + 32], u3 = su[sub + 48];
    float4 u4 = (sub < 11) ? su[sub + 64] : make_float4(0.f, 0.f, 0.f, 0.f);

    float4 a0 = make_float4(0.f,0.f,0.f,0.f), a1 = a0, a2 = a0, a3 = a0, a4 = a0;
    float4 b0 = a0, b1 = a0, b2 = a0, b3 = a0, b4 = a0;
    float den = 0.f;

#pragma unroll 4
    for (int it = 0; it < 16; it++) {
        int l = l0 + 2 * it + half;
        int tok = tok_s[l];
        const float4* row = embed4 + (long)tok * D4_;
        float4 v0 = row[sub];
        float4 v1 = row[sub + 16];
        float4 v2 = row[sub + 32];
        float4 v3 = row[sub + 48];
        float4 v4 = row[last];
        if (sub >= 11) v4 = make_float4(0.f, 0.f, 0.f, 0.f);

        float d = v0.x*u0.x + v0.y*u0.y + v0.z*u0.z + v0.w*u0.w
                + v1.x*u1.x + v1.y*u1.y + v1.z*u1.z + v1.w*u1.w
                + v2.x*u2.x + v2.y*u2.y + v2.z*u2.z + v2.w*u2.w
                + v3.x*u3.x + v3.y*u3.y + v3.z*u3.z + v3.w*u3.w
                + v4.x*u4.x + v4.y*u4.y + v4.z*u4.z + v4.w*u4.w;

        a0.x += v0.x; a0.y += v0.y; a0.z += v0.z; a0.w += v0.w;
        a1.x += v1.x; a1.y += v1.y; a1.z += v1.z; a1.w += v1.w;
        a2.x += v2.x; a2.y += v2.y; a2.z += v2.z; a2.w += v2.w;
        a3.x += v3.x; a3.y += v3.y; a3.z += v3.z; a3.w += v3.w;
        a4.x += v4.x; a4.y += v4.y; a4.z += v4.z; a4.w += v4.w;

        // 16-lane butterfly: all lanes of the half get the full dot
#pragma unroll
        for (int off = 8; off; off >>= 1) d += __shfl_xor_sync(0xffffffffu, d, off);

        float idx = (float)l;
        float lv = idx < start ? (start - idx) : (idx <= endf ? 0.f : idx - endf);
        float wv = 1.f - lv * inv_memf;
        if (!(idx < memf)) wv = 0.f;
        float e = expf(tanhf(d * wv + cq));   // logit in (-1,1): maxless softmax safe
        den += e;
        float ew = e * wv;
        if (ew != 0.f) {
            b0.x = fmaf(ew, v0.x, b0.x); b0.y = fmaf(ew, v0.y, b0.y);
            b0.z = fmaf(ew, v0.z, b0.z); b0.w = fmaf(ew, v0.w, b0.w);
            b1.x = fmaf(ew, v1.x, b1.x); b1.y = fmaf(ew, v1.y, b1.y);
            b1.z = fmaf(ew, v1.z, b1.z); b1.w = fmaf(ew, v1.w, b1.w);
            b2.x = fmaf(ew, v2.x, b2.x); b2.y = fmaf(ew, v2.y, b2.y);
            b2.z = fmaf(ew, v2.z, b2.z); b2.w = fmaf(ew, v2.w, b2.w);
            b3.x = fmaf(ew, v3.x, b3.x); b3.y = fmaf(ew, v3.y, b3.y);
            b3.z = fmaf(ew, v3.z, b3.z); b3.w = fmaf(ew, v3.w, b3.w);
            b4.x = fmaf(ew, v4.x, b4.x); b4.y = fmaf(ew, v4.y, b4.y);
            b4.z = fmaf(ew, v4.z, b4.z); b4.w = fmaf(ew, v4.w, b4.w);
        }
    }

    // merge halves (xor 16) for both accumulator sets
    a0.x += __shfl_xor_sync(0xffffffffu, a0.x, 16); a0.y += __shfl_xor_sync(0xffffffffu, a0.y, 16);
    a0.z += __shfl_xor_sync(0xffffffffu, a0.z, 16); a0.w += __shfl_xor_sync(0xffffffffu, a0.w, 16);
    a1.x += __shfl_xor_sync(0xffffffffu, a1.x, 16); a1.y += __shfl_xor_sync(0xffffffffu, a1.y, 16);
    a1.z += __shfl_xor_sync(0xffffffffu, a1.z, 16); a1.w += __shfl_xor_sync(0xffffffffu, a1.w, 16);
    a2.x += __shfl_xor_sync(0xffffffffu, a2.x, 16); a2.y += __shfl_xor_sync(0xffffffffu, a2.y, 16);
    a2.z += __shfl_xor_sync(0xffffffffu, a2.z, 16); a2.w += __shfl_xor_sync(0xffffffffu, a2.w, 16);
    a3.x += __shfl_xor_sync(0xffffffffu, a3.x, 16); a3.y += __shfl_xor_sync(0xffffffffu, a3.y, 16);
    a3.z += __shfl_xor_sync(0xffffffffu, a3.z, 16); a3.w += __shfl_xor_sync(0xffffffffu, a3.w, 16);
    a4.x += __shfl_xor_sync(0xffffffffu, a4.x, 16); a4.y += __shfl_xor_sync(0xffffffffu, a4.y, 16);
    a4.z += __shfl_xor_sync(0xffffffffu, a4.z, 16); a4.w += __shfl_xor_sync(0xffffffffu, a4.w, 16);
    b0.x += __shfl_xor_sync(0xffffffffu, b0.x, 16); b0.y += __shfl_xor_sync(0xffffffffu, b0.y, 16);
    b0.z += __shfl_xor_sync(0xffffffffu, b0.z, 16); b0.w += __shfl_xor_sync(0xffffffffu, b0.w, 16);
    b1.x += __shfl_xor_sync(0xffffffffu, b1.x, 16); b1.y += __shfl_xor_sync(0xffffffffu, b1.y, 16);
    b1.z += __shfl_xor_sync(0xffffffffu, b1.z, 16); b1.w += __shfl_xor_sync(0xffffffffu, b1.w, 16);
    b2.x += __shfl_xor_sync(0xffffffffu, b2.x, 16); b2.y += __shfl_xor_sync(0xffffffffu, b2.y, 16);
    b2.z += __shfl_xor_sync(0xffffffffu, b2.z, 16); b2.w += __shfl_xor_sync(0xffffffffu, b2.w, 16);
    b3.x += __shfl_xor_sync(0xffffffffu, b3.x, 16); b3.y += __shfl_xor_sync(0xffffffffu, b3.y, 16);
    b3.z += __shfl_xor_sync(0xffffffffu, b3.z, 16); b3.w += __shfl_xor_sync(0xffffffffu, b3.w, 16);
    b4.x += __shfl_xor_sync(0xffffffffu, b4.x, 16); b4.y += __shfl_xor_sync(0xffffffffu, b4.y, 16);
    b4.z += __shfl_xor_sync(0xffffffffu, b4.z, 16); b4.w += __shfl_xor_sync(0xffffffffu, b4.w, 16);

    if (half == 0) {
        int p0 = 4 * sub;
        atomicAdd(&red[p0 + 0], a0.x);  atomicAdd(&red[p0 + 1], a0.y);
        atomicAdd(&red[p0 + 2], a0.z);  atomicAdd(&red[p0 + 3], a0.w);
        atomicAdd(&red2[p0 + 0], b0.x); atomicAdd(&red2[p0 + 1], b0.y);
        atomicAdd(&red2[p0 + 2], b0.z); atomicAdd(&red2[p0 + 3], b0.w);
        int p1 = 4 * (sub + 16);
        atomicAdd(&red[p1 + 0], a1.x);  atomicAdd(&red[p1 + 1], a1.y);
        atomicAdd(&red[p1 + 2], a1.z);  atomicAdd(&red[p1 + 3], a1.w);
        atomicAdd(&red2[p1 + 0], b1.x); atomicAdd(&red2[p1 + 1], b1.y);
        atomicAdd(&red2[p1 + 2], b1.z); atomicAdd(&red2[p1 + 3], b1.w);
        int p2 = 4 * (sub + 32);
        atomicAdd(&red[p2 + 0], a2.x);  atomicAdd(&red[p2 + 1], a2.y);
        atomicAdd(&red[p2 + 2], a2.z);  atomicAdd(&red[p2 + 3], a2.w);
        atomicAdd(&red2[p2 + 0], b2.x); atomicAdd(&red2[p2 + 1], b2.y);
        atomicAdd(&red2[p2 + 2], b2.z); atomicAdd(&red2[p2 + 3], b2.w);
        int p3 = 4 * (sub + 48);
        atomicAdd(&red[p3 + 0], a3.x);  atomicAdd(&red[p3 + 1], a3.y);
        atomicAdd(&red[p3 + 2], a3.z);  atomicAdd(&red[p3 + 3], a3.w);
        atomicAdd(&red2[p3 + 0], b3.x); atomicAdd(&red2[p3 + 1], b3.y);
        atomicAdd(&red2[p3 + 2], b3.z); atomicAdd(&red2[p3 + 3], b3.w);
        if (sub < 11) {
            int p4 = 4 * (sub + 64);
            atomicAdd(&red[p4 + 0], a4.x);  atomicAdd(&red[p4 + 1], a4.y);
            atomicAdd(&red[p4 + 2], a4.z);  atomicAdd(&red[p4 + 3], a4.w);
            atomicAdd(&red2[p4 + 0], b4.x); atomicAdd(&red2[p4 + 1], b4.y);
            atomicAdd(&red2[p4 + 2], b4.z); atomicAdd(&red2[p4 + 3], b4.w);
        }
    }
    if (sub == 0) atomicAdd(&sden, den);   // one per half (16 tokens each)
    __syncthreads();

    float invden = 1.f / sden;
    if (tid < D_) {
        g_sumvec[b * D_ + tid] = red[tid];
        g_matt[b * D_ + tid]   = red2[tid] * invden;
    }
}

// ---------------- head phase: paired-thread split-d, shuffle combine ------------
__device__ __forceinline__ void phaseP(const float* __restrict__ W,
                                       const float* __restrict__ bias,
                                       const float* __restrict__ x,
                                       float* __restrict__ y,
                                       int k, int dh, int r, int jc,
                                       bool dotanh) {
    float4 acc = make_float4(0.f, 0.f, 0.f, 0.f);
    if (k < 300) {
        const float4* W4 = reinterpret_cast<const float4*>(W);
        const float* xr = x + r * D_;
        int d0 = dh * 150;
#pragma unroll 10
        for (int d = d0; d < d0 + 150; d++) {
            float4 w = W4[d * 75 + jc];
            float a = xr[d];
            acc.x = fmaf(a, w.x, acc.x); acc.y = fmaf(a, w.y, acc.y);
            acc.z = fmaf(a, w.z, acc.z); acc.w = fmaf(a, w.w, acc.w);
        }
    }
    acc.x += __shfl_xor_sync(0xffffffffu, acc.x, 1);
    acc.y += __shfl_xor_sync(0xffffffffu, acc.y, 1);
    acc.z += __shfl_xor_sync(0xffffffffu, acc.z, 1);
    acc.w += __shfl_xor_sync(0xffffffffu, acc.w, 1);
    if (k < 300 && dh == 0) {
        float4 b4 = reinterpret_cast<const float4*>(bias)[jc];
        acc.x += b4.x; acc.y += b4.y; acc.z += b4.z; acc.w += b4.w;
        if (dotanh) {
            acc.x = tanhf(acc.x); acc.y = tanhf(acc.y);
            acc.z = tanhf(acc.z); acc.w = tanhf(acc.w);
        }
        reinterpret_cast<float4*>(y + r * D_)[jc] = acc;
    }
    __syncthreads();
}

// ---------------- head: 64 blocks x 640 threads, R=4, paired split-d -----------
__global__ void __launch_bounds__(640, 1)
head_kernel(const float* __restrict__ Wk, const float* __restrict__ bk,
            const float* __restrict__ Wproj, const float* __restrict__ bproj,
            const float* __restrict__ Wm, const float* __restrict__ bm,
            const float* __restrict__ Wd, const float* __restrict__ bd,
            float* __restrict__ out) {
    const int R = 4;
    int b0 = blockIdx.x * R, tid = threadIdx.x;
    int k = tid >> 1, dh = tid & 1;
    int r = k / 75, jc = k % 75;
    int warp = tid >> 5, lane = tid & 31;
    __shared__ __align__(16) float sA[R * D_];
    __shared__ __align__(16) float sB[R * D_];
    __shared__ float slog[R][P_];

    for (int i = tid; i < R * D_; i += 640) sA[i] = g_matt[b0 * D_ + i];
    __syncthreads();

    phaseP(Wk, bk, sA, sB, k, dh, r, jc, false);
    phaseP(Wproj, bproj, sB, sA, k, dh, r, jc, false);
    for (int i = tid; i < R * D_; i += 640) {
        int rr = i / D_;
        sA[i] += g_sumvec[b0 * D_ + i] / (float)g_len[(b0 + rr) * 3 + 0];
    }
    __syncthreads();
    phaseP(Wm, bm, sA, sB, k, dh, r, jc, true);

    for (int idx = warp; idx < R * P_; idx += 20) {
        int rr = idx / P_, p = idx % P_;
        const float* row = sB + rr * D_;
        float s = 0.f;
#pragma unroll
        for (int kk = 0; kk < 9; kk++) {
            int j = lane + 32 * kk;
            s = fmaf(row[j], Wd[j * P_ + p], s);
        }
        if (lane < 12) {
            int j = 288 + lane;
            s = fmaf(row[j], Wd[j * P_ + p], s);
        }
#pragma unroll
        for (int off = 16; off; off >>= 1) s += __shfl_xor_sync(0xffffffffu, s, off);
        if (lane == 0) slog[rr][p] = s + bd[p];
    }
    __syncthreads();
    if (tid < R) {
        int rr = tid;
        float m = fmaxf(slog[rr][0], fmaxf(slog[rr][1], slog[rr][2]));
        float e0 = expf(slog[rr][0] - m), e1 = expf(slog[rr][1] - m), e2 = expf(slog[rr][2] - m);
        float inv = 1.f / (e0 + e1 + e2);
        out[(b0 + rr) * P_ + 0] = e0 * inv;
        out[(b0 + rr) * P_ + 1] = e1 * inv;
        out[(b0 + rr) * P_ + 2] = e2 * inv;
    }
}

extern "C" void kernel_launch(void* const* d_in, const int* in_sizes, int n_in,
                              void* d_out, int out_size) {
    const int*   text   = (const int*)d_in[0];
    const int*   aspect = (const int*)d_in[1];
    const int*   left   = (const int*)d_in[2];
    const float* embed  = (const float*)d_in[3];
    const float* Wx     = (const float*)d_in[4];
    // d_in[5] = Ws (dead in reference)
    const float* Wk     = (const float*)d_in[6];
    const float* bk     = (const float*)d_in[7];
    const float* Wq     = (const float*)d_in[8];
    const float* bq     = (const float*)d_in[9];
    const float* w_mlp  = (const float*)d_in[10];
    const float* Wproj  = (const float*)d_in[11];
    const float* bproj  = (const float*)d_in[12];
    const float* Wm     = (const float*)d_in[13];
    const float* bm     = (const float*)d_in[14];
    const float* Wd     = (const float*)d_in[15];
    const float* bd     = (const float*)d_in[16];
    float* out = (float*)d_out;

    combo_kernel<<<287, 320>>>(text, aspect, left, embed, Wk, bk, Wq, bq, w_mlp);
    mv_kernel<<<30, 320>>>(Wx, 0);
    mv_kernel<<<30, 320>>>(Wx, 1);
    mv_kernel<<<30, 320>>>(Wx, 2);
    fused_kernel<<<B_, 512>>>(text, (const float4*)embed);
    head_kernel<<<B_ / 4, 640>>>(Wk, bk, Wproj, bproj, Wm, bm, Wd, bd, out);
}